// round 1
// baseline (speedup 1.0000x reference)
#include <cuda_runtime.h>
#include <math.h>

// ---------------- problem constants ----------------
#define NCAM 12          // B6
#define CIN 256
#define HID 256
#define FH 32
#define FW 88
#define HW (FH*FW)       // 2816
#define DBINS 41
#define CTXC 32
#define NB 2             // batch
#define BCIN 192         // 6*32
#define BEV 400
#define BMID 64
#define BEVHW (BEV*BEV)  // 160000

// ---------------- scratch (device globals; no allocations) ----------------
__device__ float g_hidden[NCAM*HID*FH*FW];           // 34.6 MB
__device__ float g_context[NCAM*CTXC*FH*FW];         // 4.3 MB  == (2,192,32,88) view
__device__ float g_bev[(size_t)NB*BCIN*BEV*BEV];     // 245.8 MB
__device__ float g_y[(size_t)NB*BMID*BEV*BEV];       // 81.9 MB

// ======================================================================
// Head conv3x3 (256->256) + BN + ReLU.  Block covers (n, h, 64 oc, 88 w).
// blockDim (22,8): thread tile = 4 w x 8 oc.
// ======================================================================
__global__ __launch_bounds__(176) void head_conv3(
    const float* __restrict__ feat, const float* __restrict__ wgt,
    const float* __restrict__ bias,
    const float* __restrict__ gamma, const float* __restrict__ beta,
    const float* __restrict__ mean,  const float* __restrict__ var)
{
    const int ICB = 8;
    __shared__ float in_s[3][ICB][FW+2];   // 8.6 KB
    __shared__ float w_s[ICB][9][64];      // 18.4 KB

    const int n   = blockIdx.x / FH;
    const int h   = blockIdx.x % FH;
    const int oc0 = blockIdx.y * 64;
    const int tx  = threadIdx.x;           // 0..21 -> w tile of 4
    const int ty  = threadIdx.y;           // 0..7  -> oc group of 8
    const int tid = ty*22 + tx;

    float acc[8][4];
#pragma unroll
    for (int j = 0; j < 8; j++)
#pragma unroll
        for (int wi = 0; wi < 4; wi++) acc[j][wi] = 0.f;

    for (int ic0 = 0; ic0 < CIN; ic0 += ICB) {
        // stage input rows h-1..h+1 (with halo) for ICB channels
        for (int idx = tid; idx < 3*ICB*(FW+2); idx += 176) {
            int dy = idx / (ICB*(FW+2));
            int r  = idx - dy*ICB*(FW+2);
            int ic = r / (FW+2);
            int wl = r - ic*(FW+2);
            int hh = h - 1 + dy, ww = wl - 1;
            float v = 0.f;
            if (hh >= 0 && hh < FH && ww >= 0 && ww < FW)
                v = feat[((n*CIN + ic0+ic)*FH + hh)*FW + ww];
            in_s[dy][ic][wl] = v;
        }
        // stage weights: [ic][k][ocl]
        for (int idx = tid; idx < ICB*9*64; idx += 176) {
            int ic  = idx / 576;
            int r   = idx - ic*576;
            int k   = r / 64;
            int ocl = r - k*64;
            w_s[ic][k][ocl] = wgt[((oc0+ocl)*CIN + ic0+ic)*9 + k];
        }
        __syncthreads();

#pragma unroll
        for (int ic = 0; ic < ICB; ic++) {
#pragma unroll
            for (int dy = 0; dy < 3; dy++) {
                float iv[6];
#pragma unroll
                for (int q = 0; q < 6; q++) iv[q] = in_s[dy][ic][tx*4 + q];
#pragma unroll
                for (int dx = 0; dx < 3; dx++) {
#pragma unroll
                    for (int j = 0; j < 8; j++) {
                        float wv = w_s[ic][dy*3+dx][ty*8 + j];
#pragma unroll
                        for (int wi = 0; wi < 4; wi++)
                            acc[j][wi] = fmaf(wv, iv[wi+dx], acc[j][wi]);
                    }
                }
            }
        }
        __syncthreads();
    }

    // fused conv-bias + BN + ReLU epilogue
#pragma unroll
    for (int j = 0; j < 8; j++) {
        int oc = oc0 + ty*8 + j;
        float s = gamma[oc] * rsqrtf(var[oc] + 1e-5f);
        float t = beta[oc] + (bias[oc] - mean[oc]) * s;
#pragma unroll
        for (int wi = 0; wi < 4; wi++) {
            float v = fmaf(acc[j][wi], s, t);
            g_hidden[((n*HID + oc)*FH + h)*FW + tx*4 + wi] = fmaxf(v, 0.f);
        }
    }
}

// ======================================================================
// Head conv1x1 (256 -> Cout). Block: (n, 8-oc group); 256 threads over pixels.
// mode==1 writes to g_context, else to outp (depth_logits region of d_out).
// ======================================================================
__global__ __launch_bounds__(256) void head_conv1(
    const float* __restrict__ w, const float* __restrict__ b,
    float* __restrict__ outp, int Cout, int mode)
{
    __shared__ float ws[8][CIN];
    const int n  = blockIdx.x;
    const int o0 = blockIdx.y * 8;
    const int OB = (Cout - o0 < 8) ? (Cout - o0) : 8;
    const int tid = threadIdx.x;

    for (int idx = tid; idx < OB*CIN; idx += 256) {
        int j = idx / CIN, ic = idx - j*CIN;
        ws[j][ic] = w[(o0+j)*CIN + ic];
    }
    __syncthreads();

    float* dst = mode ? g_context : outp;
    for (int p = tid; p < HW; p += 256) {
        float acc[8];
#pragma unroll
        for (int j = 0; j < 8; j++) acc[j] = (j < OB) ? b[o0+j] : 0.f;
#pragma unroll 4
        for (int ic = 0; ic < CIN; ic++) {
            float v = g_hidden[(n*CIN + ic)*HW + p];
#pragma unroll
            for (int j = 0; j < 8; j++) acc[j] = fmaf(v, ws[j][ic], acc[j]);
        }
#pragma unroll
        for (int j = 0; j < 8; j++)
            if (j < OB) dst[(n*Cout + o0+j)*HW + p] = acc[j];
    }
}

// ======================================================================
// Bilinear resize (half-pixel centers, clamp at borders):
// (2,192,32,88) -> (2,192,400,400)
// ======================================================================
__global__ __launch_bounds__(256) void upsample_k()
{
    long idx = (long)blockIdx.x * 256 + threadIdx.x;
    const long total = (long)NB*BCIN*BEV*BEV;
    if (idx >= total) return;
    int j = (int)(idx % BEV);
    long r = idx / BEV;
    int i = (int)(r % BEV);  r /= BEV;
    int g = (int)(r % BCIN);
    int b = (int)(r / BCIN);

    float sy = (i + 0.5f) * (32.f/400.f) - 0.5f;
    float sx = (j + 0.5f) * (88.f/400.f) - 0.5f;
    int y0 = (int)floorf(sy); float fy = sy - (float)y0;
    int x0 = (int)floorf(sx); float fx = sx - (float)x0;
    int y1 = y0 + 1, x1 = x0 + 1;
    y0 = max(0, min(FH-1, y0)); y1 = max(0, min(FH-1, y1));
    x0 = max(0, min(FW-1, x0)); x1 = max(0, min(FW-1, x1));

    const float* p = g_context + ((long)b*BCIN + g) * HW;
    float v00 = p[y0*FW + x0], v01 = p[y0*FW + x1];
    float v10 = p[y1*FW + x0], v11 = p[y1*FW + x1];
    float top = v00 + (v01 - v00) * fx;
    float bot = v10 + (v11 - v10) * fx;
    g_bev[idx] = top + (bot - top) * fy;
}

// ======================================================================
// BEV conv3x3 (192 -> 64) + exact GELU. Block covers (b, h, all 64 oc, 64 w).
// blockDim (16,16): thread tile = 4 w x 4 oc.
// ======================================================================
__global__ __launch_bounds__(256) void bev_conv3(
    const float* __restrict__ bw1, const float* __restrict__ bb1)
{
    const int ICB = 12;
    __shared__ float in_s[3][ICB][66];     // 9.5 KB
    __shared__ float w_s[ICB][9][64];      // 27.6 KB

    const int wblk = blockIdx.x * 64;
    const int h    = blockIdx.y;
    const int b    = blockIdx.z;
    const int tx   = threadIdx.x;          // 0..15 -> w tile of 4
    const int ty   = threadIdx.y;          // 0..15 -> oc group of 4
    const int tid  = ty*16 + tx;

    float acc[4][4];
#pragma unroll
    for (int j = 0; j < 4; j++)
#pragma unroll
        for (int wi = 0; wi < 4; wi++) acc[j][wi] = 0.f;

    for (int ic0 = 0; ic0 < BCIN; ic0 += ICB) {
        for (int idx = tid; idx < 3*ICB*66; idx += 256) {
            int dy = idx / (ICB*66);
            int r  = idx - dy*ICB*66;
            int ic = r / 66;
            int wl = r - ic*66;
            int hh = h - 1 + dy, ww = wblk + wl - 1;
            float v = 0.f;
            if (hh >= 0 && hh < BEV && ww >= 0 && ww < BEV)
                v = g_bev[(((long)b*BCIN + ic0+ic)*BEV + hh)*BEV + ww];
            in_s[dy][ic][wl] = v;
        }
        for (int idx = tid; idx < ICB*9*64; idx += 256) {
            int ic  = idx / 576;
            int r   = idx - ic*576;
            int k   = r / 64;
            int ocl = r - k*64;
            w_s[ic][k][ocl] = bw1[(ocl*BCIN + ic0+ic)*9 + k];
        }
        __syncthreads();

#pragma unroll
        for (int ic = 0; ic < ICB; ic++) {
#pragma unroll
            for (int dy = 0; dy < 3; dy++) {
                float iv[6];
#pragma unroll
                for (int q = 0; q < 6; q++) iv[q] = in_s[dy][ic][tx*4 + q];
#pragma unroll
                for (int dx = 0; dx < 3; dx++) {
#pragma unroll
                    for (int j = 0; j < 4; j++) {
                        float wv = w_s[ic][dy*3+dx][ty*4 + j];
#pragma unroll
                        for (int wi = 0; wi < 4; wi++)
                            acc[j][wi] = fmaf(wv, iv[wi+dx], acc[j][wi]);
                    }
                }
            }
        }
        __syncthreads();
    }

#pragma unroll
    for (int j = 0; j < 4; j++) {
        int oc = ty*4 + j;
        float bv = bb1[oc];
#pragma unroll
        for (int wi = 0; wi < 4; wi++) {
            int w = wblk + tx*4 + wi;
            if (w < BEV) {
                float x = acc[j][wi] + bv;
                float gv = 0.5f * x * (1.f + erff(x * 0.70710678118654752f));
                g_y[(((long)b*BMID + oc)*BEV + h)*BEV + w] = gv;
            }
        }
    }
}

// ======================================================================
// Final conv1x1 (64 -> 64). One thread per pixel, all 64 oc in registers.
// ======================================================================
__global__ __launch_bounds__(256) void bev_conv1(
    const float* __restrict__ w, const float* __restrict__ b,
    float* __restrict__ out)
{
    __shared__ float ws[64][65];
    __shared__ float bs[64];
    const int tid = threadIdx.x;
    for (int idx = tid; idx < 4096; idx += 256) {
        int o = idx / 64, i = idx - o*64;
        ws[i][o] = w[idx];                 // w[o*64+i]
    }
    if (tid < 64) bs[tid] = b[tid];
    __syncthreads();

    const long p = (long)blockIdx.x * 256 + tid;   // 625*256 == 160000 exactly
    const int bb = blockIdx.y;

    float acc[64];
#pragma unroll
    for (int o = 0; o < 64; o++) acc[o] = bs[o];

    const float* yp = g_y + (long)bb*BMID*BEVHW + p;
#pragma unroll 4
    for (int i = 0; i < 64; i++) {
        float v = yp[(long)i*BEVHW];
#pragma unroll
        for (int o = 0; o < 64; o++) acc[o] = fmaf(v, ws[i][o], acc[o]);
    }
    float* op = out + (long)bb*BMID*BEVHW + p;
#pragma unroll
    for (int o = 0; o < 64; o++) op[(long)o*BEVHW] = acc[o];
}

// ======================================================================
extern "C" void kernel_launch(void* const* d_in, const int* in_sizes, int n_in,
                              void* d_out, int out_size)
{
    const float* feat   = (const float*)d_in[0];
    const float* dw1    = (const float*)d_in[1];
    const float* db1    = (const float*)d_in[2];
    const float* dgamma = (const float*)d_in[3];
    const float* dbeta  = (const float*)d_in[4];
    const float* dmean  = (const float*)d_in[5];
    const float* dvar   = (const float*)d_in[6];
    const float* dw2    = (const float*)d_in[7];
    const float* db2    = (const float*)d_in[8];
    const float* cw1    = (const float*)d_in[9];
    const float* cb1    = (const float*)d_in[10];
    const float* cgamma = (const float*)d_in[11];
    const float* cbeta  = (const float*)d_in[12];
    const float* cmean  = (const float*)d_in[13];
    const float* cvar   = (const float*)d_in[14];
    const float* cw2    = (const float*)d_in[15];
    const float* cb2    = (const float*)d_in[16];
    const float* bw1    = (const float*)d_in[17];
    const float* bb1    = (const float*)d_in[18];
    const float* bw2    = (const float*)d_in[19];
    const float* bb2    = (const float*)d_in[20];

    float* out = (float*)d_out;
    float* depth_logits = out + (long)NB*BMID*BEVHW;   // (12,41,32,88) after (2,64,400,400)

    dim3 hb(22, 8);
    // depth head: conv3x3+BN+ReLU -> g_hidden, then 1x1 -> depth_logits
    head_conv3<<<dim3(NCAM*FH, 4), hb>>>(feat, dw1, db1, dgamma, dbeta, dmean, dvar);
    head_conv1<<<dim3(NCAM, (DBINS+7)/8), 256>>>(dw2, db2, depth_logits, DBINS, 0);

    // context head: conv3x3+BN+ReLU -> g_hidden, then 1x1 -> g_context
    // (softmax-sum over depth bins == 1, so pooled == context exactly)
    head_conv3<<<dim3(NCAM*FH, 4), hb>>>(feat, cw1, cb1, cgamma, cbeta, cmean, cvar);
    head_conv1<<<dim3(NCAM, CTXC/8), 256>>>(cw2, cb2, nullptr, CTXC, 1);

    // bilinear upsample (reshape is a pure view of g_context)
    {
        long total = (long)NB*BCIN*BEV*BEV;
        int blocks = (int)((total + 255) / 256);
        upsample_k<<<blocks, 256>>>();
    }

    // bev conv3x3 + GELU, then final 1x1
    bev_conv3<<<dim3(7, BEV, NB), dim3(16, 16)>>>(bw1, bb1);
    bev_conv1<<<dim3(BEVHW/256, NB), 256>>>(bw2, bb2, out);
}

// round 2
// speedup vs baseline: 1.4102x; 1.4102x over previous
#include <cuda_runtime.h>
#include <math.h>

// ---------------- problem constants ----------------
#define NCAM 12          // B6
#define CIN 256
#define HID 256
#define FH 32
#define FW 88
#define HW (FH*FW)       // 2816
#define DBINS 41
#define CTXC 32
#define NB 2             // batch
#define BCIN 192         // 6*32
#define BEV 400
#define BMID 64
#define BEVHW (BEV*BEV)  // 160000

// ---------------- scratch (device globals; no allocations) ----------------
__device__ float g_hidden[2*NCAM*HID*FH*FW];         // both heads
__device__ float g_context[NCAM*CTXC*FH*FW];         // == (2,192,32,88) view
__device__ float g_bev[(size_t)NB*BCIN*BEV*BEV];     // 245.8 MB
__device__ float g_wt_d[CIN*9*HID];                  // dw1 transposed [ic][k][oc]
__device__ float g_wt_c[CIN*9*HID];                  // cw1 transposed
__device__ float g_wt_b[BCIN*9*BMID];                // bw1 transposed
__device__ float g_w2t[BMID*BMID];                   // bw2 transposed [i][o]

// ======================================================================
// Weight transposes: [oc][ic][3][3] -> [ic][k][oc]   (coalesced staging later)
// ======================================================================
__global__ void transpose_w(const float* __restrict__ w, float* __restrict__ o,
                            int OC, int IC)
{
    int idx = blockIdx.x*256 + threadIdx.x;
    if (idx >= OC*IC*9) return;
    int oc = idx / (IC*9);
    int r  = idx - oc*IC*9;
    int ic = r / 9;
    int k  = r - ic*9;
    o[(ic*9 + k)*OC + oc] = w[idx];
}

__global__ void transpose_w2(const float* __restrict__ w, float* __restrict__ o)
{
    int idx = threadIdx.x + blockIdx.x*256;  // 4096
    if (idx >= BMID*BMID) return;
    int oc = idx / BMID, ic = idx - oc*BMID;
    o[ic*BMID + oc] = w[idx];
}

// ======================================================================
// Head conv3x3 (256->256) + BN + ReLU, both heads (blockIdx.z).
// Block: (n, h, 64 oc, 88 w). blockDim (22,8): thread tile = 4w x 8oc.
// ======================================================================
#define ICB 8
#define INPAD 92   // FW+2 padded to 16B multiple

__global__ __launch_bounds__(176) void head_conv3(
    const float* __restrict__ feat,
    const float* __restrict__ bias_d, const float* __restrict__ gam_d,
    const float* __restrict__ bet_d,  const float* __restrict__ mu_d,
    const float* __restrict__ var_d,
    const float* __restrict__ bias_c, const float* __restrict__ gam_c,
    const float* __restrict__ bet_c,  const float* __restrict__ mu_c,
    const float* __restrict__ var_c)
{
    __shared__ __align__(16) float sm[3*ICB*INPAD + ICB*9*64];
    float* in_s = sm;                      // [3][ICB][INPAD]
    float* w_s  = sm + 3*ICB*INPAD;        // [ICB][9][64]

    const int head = blockIdx.z;
    const float* wt   = head ? g_wt_c : g_wt_d;
    const float* bias = head ? bias_c : bias_d;
    const float* gam  = head ? gam_c  : gam_d;
    const float* bet  = head ? bet_c  : bet_d;
    const float* mu   = head ? mu_c   : mu_d;
    const float* var  = head ? var_c  : var_d;
    float* dst = g_hidden + (size_t)head*NCAM*HID*HW;

    const int n   = blockIdx.x / FH;
    const int h   = blockIdx.x % FH;
    const int oc0 = blockIdx.y * 64;
    const int tx  = threadIdx.x;           // 0..21 -> w tile of 4
    const int ty  = threadIdx.y;           // 0..7  -> oc group of 8
    const int tid = ty*22 + tx;

    float acc[8][4];
#pragma unroll
    for (int j = 0; j < 8; j++)
#pragma unroll
        for (int wi = 0; wi < 4; wi++) acc[j][wi] = 0.f;

    for (int ic0 = 0; ic0 < CIN; ic0 += ICB) {
        // stage input rows h-1..h+1 (halo) for ICB channels
        for (int idx = tid; idx < 3*ICB*(FW+2); idx += 176) {
            int dy = idx / (ICB*(FW+2));
            int r  = idx - dy*ICB*(FW+2);
            int ic = r / (FW+2);
            int wl = r - ic*(FW+2);
            int hh = h - 1 + dy, ww = wl - 1;
            float v = 0.f;
            if (hh >= 0 && hh < FH && ww >= 0 && ww < FW)
                v = feat[((n*CIN + ic0+ic)*FH + hh)*FW + ww];
            in_s[(dy*ICB + ic)*INPAD + wl] = v;
        }
        // stage weights (coalesced from transposed layout)
        for (int idx = tid; idx < ICB*9*64; idx += 176) {
            int ic  = idx / 576;
            int r   = idx - ic*576;
            int k   = r / 64;
            int ocl = r - k*64;
            w_s[(ic*9 + k)*64 + ocl] = wt[((ic0+ic)*9 + k)*HID + oc0 + ocl];
        }
        __syncthreads();

#pragma unroll
        for (int ic = 0; ic < ICB; ic++) {
#pragma unroll
            for (int dy = 0; dy < 3; dy++) {
                const float* row = &in_s[(dy*ICB + ic)*INPAD + tx*4];
                float4 a = *reinterpret_cast<const float4*>(row);
                float2 b = *reinterpret_cast<const float2*>(row + 4);
                float iv[6] = {a.x, a.y, a.z, a.w, b.x, b.y};
#pragma unroll
                for (int dx = 0; dx < 3; dx++) {
                    const float* wrow = &w_s[(ic*9 + dy*3 + dx)*64 + ty*8];
                    float4 w0 = *reinterpret_cast<const float4*>(wrow);
                    float4 w1 = *reinterpret_cast<const float4*>(wrow + 4);
                    float wv[8] = {w0.x,w0.y,w0.z,w0.w,w1.x,w1.y,w1.z,w1.w};
#pragma unroll
                    for (int j = 0; j < 8; j++)
#pragma unroll
                        for (int wi = 0; wi < 4; wi++)
                            acc[j][wi] = fmaf(wv[j], iv[wi+dx], acc[j][wi]);
                }
            }
        }
        __syncthreads();
    }

    // fused conv-bias + BN + ReLU epilogue
#pragma unroll
    for (int j = 0; j < 8; j++) {
        int oc = oc0 + ty*8 + j;
        float s = gam[oc] * rsqrtf(var[oc] + 1e-5f);
        float t = bet[oc] + (bias[oc] - mu[oc]) * s;
        float4 o;
        float* v = &o.x;
#pragma unroll
        for (int wi = 0; wi < 4; wi++)
            v[wi] = fmaxf(fmaf(acc[j][wi], s, t), 0.f);
        *reinterpret_cast<float4*>(&dst[((n*HID + oc)*FH + h)*FW + tx*4]) = o;
    }
}

// ======================================================================
// Head conv1x1 (256 -> Cout), both heads, parallel over pixels.
// grid (11, 6, 24): pixel chunk x oc-group x (head*NCAM+n)
// ======================================================================
__global__ __launch_bounds__(256) void head_conv1(
    const float* __restrict__ dw2, const float* __restrict__ db2,
    const float* __restrict__ cw2, const float* __restrict__ cb2,
    float* __restrict__ depth_out)
{
    const int head = blockIdx.z >= NCAM;
    const int n    = blockIdx.z - head*NCAM;
    if (head && blockIdx.y >= 4) return;   // ctx has 32 oc = 4 groups

    const int Cout = head ? CTXC : DBINS;
    const float* w = head ? cw2 : dw2;
    const float* b = head ? cb2 : db2;
    const float* src = g_hidden + (size_t)head*NCAM*HID*HW + (size_t)n*HID*HW;
    float* dst = head ? (g_context + (size_t)n*CTXC*HW) : (depth_out + (size_t)n*DBINS*HW);

    const int o0 = blockIdx.y * 8;
    const int OB = (Cout - o0 < 8) ? (Cout - o0) : 8;
    const int tid = threadIdx.x;
    const int p = blockIdx.x*256 + tid;    // HW = 11*256 exactly

    __shared__ float ws[8][CIN];
    for (int idx = tid; idx < OB*CIN; idx += 256) {
        int j = idx / CIN, ic = idx - j*CIN;
        ws[j][ic] = w[(o0+j)*CIN + ic];
    }
    __syncthreads();

    float acc[8];
#pragma unroll
    for (int j = 0; j < 8; j++) acc[j] = 0.f;
#pragma unroll 8
    for (int ic = 0; ic < CIN; ic++) {
        float v = src[ic*HW + p];
#pragma unroll
        for (int j = 0; j < 8; j++) acc[j] = fmaf(v, ws[j][ic], acc[j]);
    }
#pragma unroll
    for (int j = 0; j < 8; j++)
        if (j < OB) dst[(o0+j)*HW + p] = acc[j] + b[o0+j];
}

// ======================================================================
// Bilinear resize (half-pixel centers, clamp): (2,192,32,88)->(2,192,400,400)
// float4 stores (BEV = 400 = 100*4)
// ======================================================================
__global__ __launch_bounds__(256) void upsample_k()
{
    long idx = (long)blockIdx.x * 256 + threadIdx.x;
    const long total = (long)NB*BCIN*BEV*100;
    if (idx >= total) return;
    int q = (int)(idx % 100);
    long r = idx / 100;
    int i = (int)(r % BEV);  r /= BEV;
    int g = (int)(r % BCIN);
    int b = (int)(r / BCIN);

    float sy = (i + 0.5f) * (32.f/400.f) - 0.5f;
    int y0 = (int)floorf(sy); float fy = sy - (float)y0;
    int y1 = y0 + 1;
    y0 = max(0, min(FH-1, y0)); y1 = max(0, min(FH-1, y1));
    const float* p0 = g_context + ((long)b*BCIN + g)*HW + y0*FW;
    const float* p1 = g_context + ((long)b*BCIN + g)*HW + y1*FW;

    float4 o;
    float* ov = &o.x;
#pragma unroll
    for (int c = 0; c < 4; c++) {
        int j = q*4 + c;
        float sx = (j + 0.5f) * (88.f/400.f) - 0.5f;
        int x0 = (int)floorf(sx); float fx = sx - (float)x0;
        int x1 = x0 + 1;
        x0 = max(0, min(FW-1, x0)); x1 = max(0, min(FW-1, x1));
        float t = p0[x0] + (p0[x1] - p0[x0]) * fx;
        float bo = p1[x0] + (p1[x1] - p1[x0]) * fx;
        ov[c] = t + (bo - t) * fy;
    }
    *reinterpret_cast<float4*>(&g_bev[(((long)b*BCIN + g)*BEV + i)*BEV + q*4]) = o;
}

// ======================================================================
// BEV conv3x3 (192->64) + GELU + conv1x1 (64->64), fully fused.
// Block covers (b, h, 64 w, all oc). blockDim (16,16): tile 4w x 4oc.
// ======================================================================
#define BICB 12
#define BINPAD 68

__global__ __launch_bounds__(256) void bev_fused(
    const float* __restrict__ bb1, const float* __restrict__ bb2,
    float* __restrict__ out)
{
    __shared__ __align__(16) float sm[3*BICB*BINPAD + BICB*9*64]; // 9360 floats
    float* in_s = sm;                         // [3][BICB][BINPAD]
    float* w_s  = sm + 3*BICB*BINPAD;         // [BICB][9][64]
    // phase-2 overlay
    float* s_ex = sm;                         // [64][68]
    float* w2s  = sm + 64*68;                 // [64][64]
    float* b2s  = sm + 64*68 + 64*64;         // [64]

    const int wblk = blockIdx.x * 64;
    const int h    = blockIdx.y;
    const int b    = blockIdx.z;
    const int tx   = threadIdx.x;             // 0..15 -> w tile of 4
    const int ty   = threadIdx.y;             // 0..15 -> oc group of 4
    const int tid  = ty*16 + tx;

    float acc[4][4];
#pragma unroll
    for (int j = 0; j < 4; j++)
#pragma unroll
        for (int wi = 0; wi < 4; wi++) acc[j][wi] = 0.f;

    for (int ic0 = 0; ic0 < BCIN; ic0 += BICB) {
        for (int idx = tid; idx < 3*BICB*66; idx += 256) {
            int dy = idx / (BICB*66);
            int r  = idx - dy*BICB*66;
            int ic = r / 66;
            int wl = r - ic*66;
            int hh = h - 1 + dy, ww = wblk + wl - 1;
            float v = 0.f;
            if (hh >= 0 && hh < BEV && ww >= 0 && ww < BEV)
                v = g_bev[(((long)b*BCIN + ic0+ic)*BEV + hh)*BEV + ww];
            in_s[(dy*BICB + ic)*BINPAD + wl] = v;
        }
        for (int idx = tid; idx < BICB*9*64; idx += 256) {
            int ic  = idx / 576;
            int r   = idx - ic*576;
            int k   = r / 64;
            int ocl = r - k*64;
            w_s[(ic*9 + k)*64 + ocl] = g_wt_b[((ic0+ic)*9 + k)*BMID + ocl];
        }
        __syncthreads();

#pragma unroll
        for (int ic = 0; ic < BICB; ic++) {
#pragma unroll
            for (int dy = 0; dy < 3; dy++) {
                const float* row = &in_s[(dy*BICB + ic)*BINPAD + tx*4];
                float4 a = *reinterpret_cast<const float4*>(row);
                float2 b2v = *reinterpret_cast<const float2*>(row + 4);
                float iv[6] = {a.x, a.y, a.z, a.w, b2v.x, b2v.y};
#pragma unroll
                for (int dx = 0; dx < 3; dx++) {
                    float4 w0 = *reinterpret_cast<const float4*>(
                        &w_s[(ic*9 + dy*3 + dx)*64 + ty*4]);
                    float wv[4] = {w0.x, w0.y, w0.z, w0.w};
#pragma unroll
                    for (int j = 0; j < 4; j++)
#pragma unroll
                        for (int wi = 0; wi < 4; wi++)
                            acc[j][wi] = fmaf(wv[j], iv[wi+dx], acc[j][wi]);
                }
            }
        }
        __syncthreads();
    }

    // ---- phase 2: GELU -> smem exchange -> 1x1 (64->64) -> gmem ----
    __syncthreads();   // everyone done reading in_s/w_s

    {
        // write GELU(conv+bias) to s_ex[oc][w_local]
#pragma unroll
        for (int j = 0; j < 4; j++) {
            int oc = ty*4 + j;
            float bv = bb1[oc];
#pragma unroll
            for (int wi = 0; wi < 4; wi++) {
                float x = acc[j][wi] + bv;
                s_ex[oc*BINPAD + tx*4 + wi] =
                    0.5f * x * (1.f + erff(x * 0.70710678118654752f));
            }
        }
        // stage transposed 1x1 weights + bias
        for (int idx = tid; idx < BMID*BMID; idx += 256)
            w2s[idx] = g_w2t[idx];
        if (tid < BMID) b2s[tid] = bb2[tid];
    }
    __syncthreads();

    float acc2[4][4];
#pragma unroll
    for (int j = 0; j < 4; j++)
#pragma unroll
        for (int wi = 0; wi < 4; wi++) acc2[j][wi] = b2s[ty*4 + j];

#pragma unroll 8
    for (int i = 0; i < BMID; i++) {
        float4 sv = *reinterpret_cast<const float4*>(&s_ex[i*BINPAD + tx*4]);
        float4 wv = *reinterpret_cast<const float4*>(&w2s[i*BMID + ty*4]);
        float svv[4] = {sv.x, sv.y, sv.z, sv.w};
        float wvv[4] = {wv.x, wv.y, wv.z, wv.w};
#pragma unroll
        for (int j = 0; j < 4; j++)
#pragma unroll
            for (int wi = 0; wi < 4; wi++)
                acc2[j][wi] = fmaf(wvv[j], svv[wi], acc2[j][wi]);
    }

    const int wbase = wblk + tx*4;
    if (wbase + 3 < BEV) {
#pragma unroll
        for (int j = 0; j < 4; j++) {
            int oc = ty*4 + j;
            float4 o = {acc2[j][0], acc2[j][1], acc2[j][2], acc2[j][3]};
            *reinterpret_cast<float4*>(
                &out[(((long)b*BMID + oc)*BEV + h)*BEV + wbase]) = o;
        }
    } else {
#pragma unroll
        for (int j = 0; j < 4; j++) {
            int oc = ty*4 + j;
#pragma unroll
            for (int wi = 0; wi < 4; wi++)
                if (wbase + wi < BEV)
                    out[(((long)b*BMID + oc)*BEV + h)*BEV + wbase + wi] = acc2[j][wi];
        }
    }
}

// ======================================================================
extern "C" void kernel_launch(void* const* d_in, const int* in_sizes, int n_in,
                              void* d_out, int out_size)
{
    const float* feat   = (const float*)d_in[0];
    const float* dw1    = (const float*)d_in[1];
    const float* db1    = (const float*)d_in[2];
    const float* dgamma = (const float*)d_in[3];
    const float* dbeta  = (const float*)d_in[4];
    const float* dmean  = (const float*)d_in[5];
    const float* dvar   = (const float*)d_in[6];
    const float* dw2    = (const float*)d_in[7];
    const float* db2    = (const float*)d_in[8];
    const float* cw1    = (const float*)d_in[9];
    const float* cb1    = (const float*)d_in[10];
    const float* cgamma = (const float*)d_in[11];
    const float* cbeta  = (const float*)d_in[12];
    const float* cmean  = (const float*)d_in[13];
    const float* cvar   = (const float*)d_in[14];
    const float* cw2    = (const float*)d_in[15];
    const float* cb2    = (const float*)d_in[16];
    const float* bw1    = (const float*)d_in[17];
    const float* bb1    = (const float*)d_in[18];
    const float* bw2    = (const float*)d_in[19];
    const float* bb2    = (const float*)d_in[20];

    float* out = (float*)d_out;
    float* depth_logits = out + (long)NB*BMID*BEVHW;   // (12,41,32,88)

    float *p_wt_d, *p_wt_c, *p_wt_b, *p_w2t;
    cudaGetSymbolAddress((void**)&p_wt_d, g_wt_d);
    cudaGetSymbolAddress((void**)&p_wt_c, g_wt_c);
    cudaGetSymbolAddress((void**)&p_wt_b, g_wt_b);
    cudaGetSymbolAddress((void**)&p_w2t,  g_w2t);

    // weight preprocessing (coalesced staging layouts)
    transpose_w<<<(HID*CIN*9 + 255)/256, 256>>>(dw1, p_wt_d, HID, CIN);
    transpose_w<<<(HID*CIN*9 + 255)/256, 256>>>(cw1, p_wt_c, HID, CIN);
    transpose_w<<<(BMID*BCIN*9 + 255)/256, 256>>>(bw1, p_wt_b, BMID, BCIN);
    transpose_w2<<<(BMID*BMID + 255)/256, 256>>>(bw2, p_w2t);

    // both head conv3x3 (+BN+ReLU) in one launch
    head_conv3<<<dim3(NCAM*FH, 4, 2), dim3(22, 8)>>>(
        feat, db1, dgamma, dbeta, dmean, dvar,
              cb1, cgamma, cbeta, cmean, cvar);

    // both head 1x1 convs (softmax-sum == 1, so pooled == context)
    head_conv1<<<dim3(11, 6, 2*NCAM), 256>>>(dw2, db2, cw2, cb2, depth_logits);

    // bilinear upsample (reshape is a pure view of g_context)
    {
        long total = (long)NB*BCIN*BEV*100;
        upsample_k<<<(int)((total + 255)/256), 256>>>();
    }

    // bev conv3x3 + GELU + 1x1 fused
    bev_fused<<<dim3(7, BEV, NB), dim3(16, 16)>>>(bb1, bb2, out);
}